// round 2
// baseline (speedup 1.0000x reference)
#include <cuda_runtime.h>

// ---------------- scratch (device globals; no allocations allowed) ----------
__device__ float g_t1 [8 * 32 * 128 * 128];      // project1 conv1 out (ReLU)
__device__ float g_g  [8 * 32 * 128 * 128];      // guidance conv1 out (ReLU)
__device__ float g_xp [8 * 16 * 128 * 128];      // project1 conv2 out (ReLU)
__device__ float g_wts[8 * 16 * 9 * 128 * 128];  // softmax weights, layout (n, pq, k, hw)
__device__ float g_up [8 * 16 * 512 * 512];      // upsampled (pixel-shuffled) NCHW
__device__ float g_mid[8 *  8 * 512 * 512];      // project2 conv1 out (ReLU)

// ---------------- generic direct conv: 16x16 tile, CB out-channels/block ----
template <int CIN, int COUT_TOTAL, int CB, int K, bool RELU>
__global__ __launch_bounds__(256, 2)
void conv2d_kernel(const float* __restrict__ in,
                   const float* __restrict__ wgt,
                   const float* __restrict__ bias,
                   float* __restrict__ out,
                   int H, int W)
{
    constexpr int TILE = 16;
    constexpr int S    = TILE + K - 1;
    constexpr int PAD  = K / 2;
    constexpr int KK   = K * K;
    constexpr int NGRP = COUT_TOTAL / CB;

    __shared__ float s_in[S * S];
    __shared__ float s_w[KK * CB];     // [k][co] layout for vectorizable LDS

    const int n   = blockIdx.z / NGRP;
    const int grp = blockIdx.z % NGRP;
    const int h0  = blockIdx.y * TILE;
    const int w0  = blockIdx.x * TILE;
    const int tx  = threadIdx.x, ty = threadIdx.y;
    const int tid = ty * TILE + tx;

    float acc[CB];
#pragma unroll
    for (int co = 0; co < CB; co++) acc[co] = bias[grp * CB + co];

    for (int cin = 0; cin < CIN; cin++) {
        __syncthreads();
        // input tile (zero-padded)
        for (int i = tid; i < S * S; i += TILE * TILE) {
            int r = i / S, c = i % S;
            int gh = h0 + r - PAD, gw = w0 + c - PAD;
            float v = 0.f;
            if (gh >= 0 && gh < H && gw >= 0 && gw < W)
                v = in[((n * CIN + cin) * H + gh) * W + gw];
            s_in[i] = v;
        }
        // weight slice for this cin, transposed to [k][co]
        for (int i = tid; i < KK * CB; i += TILE * TILE) {
            int co = i % CB, kidx = i / CB;
            s_w[i] = wgt[((grp * CB + co) * CIN + cin) * KK + kidx];
        }
        __syncthreads();

#pragma unroll
        for (int kh = 0; kh < K; kh++) {
#pragma unroll
            for (int kw = 0; kw < K; kw++) {
                float v = s_in[(ty + kh) * S + (tx + kw)];
                const float* wp = &s_w[(kh * K + kw) * CB];
#pragma unroll
                for (int co = 0; co < CB; co++)
                    acc[co] = fmaf(v, wp[co], acc[co]);
            }
        }
    }

    const int h = h0 + ty, w = w0 + tx;
#pragma unroll
    for (int co = 0; co < CB; co++) {
        float v = acc[co];
        if (RELU) v = fmaxf(v, 0.f);
        out[((n * COUT_TOTAL + grp * CB + co) * H + h) * W + w] = v;
    }
}

// -------- fused pair of 64->32 k3 convs sharing the same input x -----------
// blockIdx.z low bit selects which weight/bias/output set; input tile logic
// identical to conv2d_kernel (CIN=64, CB=32, K=3).
__global__ __launch_bounds__(256, 2)
void conv_dual64to32_kernel(const float* __restrict__ in,
                            const float* __restrict__ wA,
                            const float* __restrict__ bA,
                            float* __restrict__ outA,
                            const float* __restrict__ wB,
                            const float* __restrict__ bB,
                            float* __restrict__ outB)
{
    constexpr int H = 128, W = 128, TILE = 16, S = 18, CB = 32, CIN = 64;

    __shared__ float s_in[S * S];
    __shared__ float s_w[9 * CB];

    const int which = blockIdx.z & 1;
    const int n   = blockIdx.z >> 1;
    const float* wgt  = which ? wB : wA;
    const float* bias = which ? bB : bA;
    float*       out  = which ? outB : outA;

    const int h0 = blockIdx.y * TILE;
    const int w0 = blockIdx.x * TILE;
    const int tx = threadIdx.x, ty = threadIdx.y;
    const int tid = ty * TILE + tx;

    float acc[CB];
#pragma unroll
    for (int co = 0; co < CB; co++) acc[co] = bias[co];

    for (int cin = 0; cin < CIN; cin++) {
        __syncthreads();
        for (int i = tid; i < S * S; i += 256) {
            int r = i / S, c = i % S;
            int gh = h0 + r - 1, gw = w0 + c - 1;
            float v = 0.f;
            if (gh >= 0 && gh < H && gw >= 0 && gw < W)
                v = in[((n * CIN + cin) * H + gh) * W + gw];
            s_in[i] = v;
        }
        for (int i = tid; i < 9 * CB; i += 256) {
            int co = i % CB, kidx = i / CB;
            s_w[i] = wgt[(co * CIN + cin) * 9 + kidx];
        }
        __syncthreads();

#pragma unroll
        for (int kh = 0; kh < 3; kh++) {
#pragma unroll
            for (int kw = 0; kw < 3; kw++) {
                float v = s_in[(ty + kh) * S + (tx + kw)];
                const float* wp = &s_w[(kh * 3 + kw) * CB];
#pragma unroll
                for (int co = 0; co < CB; co++)
                    acc[co] = fmaf(v, wp[co], acc[co]);
            }
        }
    }

    const int h = h0 + ty, w = w0 + tx;
#pragma unroll
    for (int co = 0; co < CB; co++)
        out[((n * 32 + co) * H + h) * W + w] = fmaxf(acc[co], 0.f);
}

// ------------- guidance 1x1 conv (32->144) + per-(p,q) softmax over 9 -------
// wts output layout: [((n*16 + pq)*9 + k) * HW + hw]   (pq = p*4+q, k = i*3+j)
__global__ void gw_softmax_kernel(const float* __restrict__ g,
                                  const float* __restrict__ w2,
                                  const float* __restrict__ b2,
                                  float* __restrict__ wts)
{
    constexpr int HW = 128 * 128;
    __shared__ float s_w[144 * 32];
    __shared__ float s_b[144];
    for (int i = threadIdx.x; i < 144 * 32; i += 256) s_w[i] = w2[i];
    for (int i = threadIdx.x; i < 144;      i += 256) s_b[i] = b2[i];
    __syncthreads();

    const int pix = blockIdx.x * 256 + threadIdx.x;   // exactly 8*16384 pixels
    const int n = pix / HW, hw = pix % HW;

    float gv[32];
#pragma unroll
    for (int c = 0; c < 32; c++) gv[c] = g[(n * 32 + c) * HW + hw];

    for (int pq = 0; pq < 16; pq++) {
        float v[9];
#pragma unroll
        for (int k = 0; k < 9; k++) {
            const int ch = k * 16 + pq;     // reference channel order: k*16 + p*4 + q
            float acc = s_b[ch];
            const float* wp = &s_w[ch * 32];
#pragma unroll
            for (int c = 0; c < 32; c++) acc = fmaf(gv[c], wp[c], acc);
            v[k] = acc;
        }
        float m = v[0];
#pragma unroll
        for (int k = 1; k < 9; k++) m = fmaxf(m, v[k]);
        float s = 0.f;
#pragma unroll
        for (int k = 0; k < 9; k++) { v[k] = __expf(v[k] - m); s += v[k]; }
        const float inv = 1.f / s;
#pragma unroll
        for (int k = 0; k < 9; k++)
            wts[((n * 16 + pq) * 9 + k) * HW + hw] = v[k] * inv;
    }
}

// ------------- convex upsample + pixel shuffle ------------------------------
// grid: (W/16, H, N); block: (64, 4). Each thread = one high-res output column.
__global__ void upsample_kernel(const float* __restrict__ xp,
                                const float* __restrict__ wts,
                                float* __restrict__ up)
{
    constexpr int H = 128, W = 128, HW = H * W;
    __shared__ float s_xp[16][3][18];   // [c][row -1..+1][col wtile-1 .. wtile+16]

    const int n = blockIdx.z, h = blockIdx.y, wtile = blockIdx.x * 16;
    const int tid = threadIdx.y * 64 + threadIdx.x;

    for (int i = tid; i < 16 * 3 * 18; i += 256) {
        int c = i / 54, rem = i % 54, r = rem / 18, col = rem % 18;
        int gh = h + r - 1, gw = wtile + col - 1;
        float v = 0.f;
        if (gh >= 0 && gh < H && gw >= 0 && gw < W)
            v = xp[(n * 16 + c) * HW + gh * W + gw];
        s_xp[c][r][col] = v;
    }
    __syncthreads();

    const int p  = threadIdx.y;          // 0..3
    const int q  = threadIdx.x & 3;      // 0..3
    const int wl = threadIdx.x >> 2;     // 0..15 local low-res col
    const int pq = p * 4 + q;
    const int hw = h * W + wtile + wl;

    float wt[9];
#pragma unroll
    for (int k = 0; k < 9; k++) wt[k] = wts[((n * 16 + pq) * 9 + k) * HW + hw];

    const int h_hi = h * 4 + p;
    const int w_hi = (wtile + wl) * 4 + q;
#pragma unroll
    for (int c = 0; c < 16; c++) {
        float acc = 0.f;
#pragma unroll
        for (int i = 0; i < 3; i++)
#pragma unroll
            for (int j = 0; j < 3; j++)
                acc = fmaf(wt[i * 3 + j], s_xp[c][i][wl + j], acc);
        up[((n * 16 + c) * 512 + h_hi) * 512 + w_hi] = acc;   // coalesced in w_hi
    }
}

// ---------------------------------------------------------------------------
extern "C" void kernel_launch(void* const* d_in, const int* in_sizes, int n_in,
                              void* d_out, int out_size)
{
    const float* x     = (const float*)d_in[0];
    const float* p1_w1 = (const float*)d_in[1];
    const float* p1_b1 = (const float*)d_in[2];
    const float* p1_w2 = (const float*)d_in[3];
    const float* p1_b2 = (const float*)d_in[4];
    const float* gw_w1 = (const float*)d_in[5];
    const float* gw_b1 = (const float*)d_in[6];
    const float* gw_w2 = (const float*)d_in[7];
    const float* gw_b2 = (const float*)d_in[8];
    const float* p2_w1 = (const float*)d_in[9];
    const float* p2_b1 = (const float*)d_in[10];
    const float* p2_w2 = (const float*)d_in[11];
    const float* p2_b2 = (const float*)d_in[12];
    float* out = (float*)d_out;

    float *t1, *gg, *xp, *wts, *up, *mid;
    cudaGetSymbolAddress((void**)&t1,  g_t1);
    cudaGetSymbolAddress((void**)&gg,  g_g);
    cudaGetSymbolAddress((void**)&xp,  g_xp);
    cudaGetSymbolAddress((void**)&wts, g_wts);
    cudaGetSymbolAddress((void**)&up,  g_up);
    cudaGetSymbolAddress((void**)&mid, g_mid);

    dim3 b16(16, 16);

    // project1 conv1 + guidance conv1 fused (both 64->32, k3, ReLU, same input)
    conv_dual64to32_kernel<<<dim3(8, 8, 16), b16>>>(x, p1_w1, p1_b1, t1,
                                                    gw_w1, gw_b1, gg);
    // project1 conv2 (32->16, k3, ReLU)
    conv2d_kernel<32, 16, 16, 3, true><<<dim3(8, 8, 8), b16>>>(t1, p1_w2, p1_b2, xp, 128, 128);
    // guidance 1x1 (32->144) + group softmax
    gw_softmax_kernel<<<512, 256>>>(gg, gw_w2, gw_b2, wts);
    // convex upsample + pixel shuffle -> (8,16,512,512)
    upsample_kernel<<<dim3(8, 128, 8), dim3(64, 4)>>>(xp, wts, up);
    // project2 conv1 (16->8, k5, ReLU) on 512x512
    conv2d_kernel<16, 8, 8, 5, true><<<dim3(32, 32, 8), b16>>>(up, p2_w1, p2_b1, mid, 512, 512);
    // project2 conv2 (8->64, k3) -> output, split into 2 co-groups of 32
    conv2d_kernel<8, 64, 32, 3, false><<<dim3(32, 32, 16), b16>>>(mid, p2_w2, p2_b2, out, 512, 512);
}